// round 6
// baseline (speedup 1.0000x reference)
#include <cuda_runtime.h>
#include <math.h>

#define Bz   32
#define Lz   256
#define DN   512
#define DE   64
#define FNh  1024
#define NTOK (Bz*Lz)
#define NROWS ((size_t)NTOK*Lz)
#define EPSF 1e-5f

typedef unsigned long long u64t;

__device__ __forceinline__ u64t pk2(float lo, float hi){
    u64t r; asm("mov.b64 %0,{%1,%2};" : "=l"(r) : "f"(lo), "f"(hi)); return r;
}
__device__ __forceinline__ void up2(u64t v, float& a, float& b){
    asm("mov.b64 {%0,%1},%2;" : "=f"(a), "=f"(b) : "l"(v));
}
__device__ __forceinline__ u64t fma2(u64t a, u64t b, u64t c){
    u64t d; asm("fma.rn.f32x2 %0,%1,%2,%3;" : "=l"(d) : "l"(a), "l"(b), "l"(c)); return d;
}
__device__ __forceinline__ float eluf(float x){
    return x > 0.f ? x : (__expf(x) - 1.f);
}

// ------------------------- scratch (device globals) -------------------------
__device__ __align__(16) float g_hln [NTOK*DN];
__device__ __align__(16) float g_qkv [(size_t)NTOK*3*DN];
__device__ __align__(16) float g_kT  [(size_t)Bz*DN*Lz];      // [b][dh][m]
__device__ __align__(16) float g_vatt[NTOK*DN];
__device__ __align__(16) float g_h2  [NTOK*DN];
__device__ __align__(16) float g_hff [NTOK*DN];
__device__ __align__(16) float g_t1  [(size_t)NTOK*FNh];
__device__ __align__(16) float g_e2  [NROWS*DE];              // 537 MB
__device__ __align__(16) float g_hid [NROWS*128];             // 1073 MB

// ------------------------- LN over 512 ------------------
__global__ __launch_bounds__(256) void ln512_kernel(
    const float* __restrict__ x, const float* __restrict__ g,
    const float* __restrict__ bta, float* __restrict__ y)
{
    __shared__ float r1[8], r2[8];
    int row = blockIdx.x, t = threadIdx.x;
    const float* xr = x + (size_t)row * DN;
    float2 v = *(const float2*)(xr + 2*t);
    float s = v.x + v.y;
    #pragma unroll
    for (int o = 16; o; o >>= 1) s += __shfl_xor_sync(0xffffffffu, s, o);
    if ((t & 31) == 0) r1[t >> 5] = s;
    __syncthreads();
    float tot = 0.f;
    #pragma unroll
    for (int i = 0; i < 8; i++) tot += r1[i];
    float mean = tot * (1.f/512.f);
    float d0 = v.x - mean, d1 = v.y - mean;
    float q = d0*d0 + d1*d1;
    #pragma unroll
    for (int o = 16; o; o >>= 1) q += __shfl_xor_sync(0xffffffffu, q, o);
    if ((t & 31) == 0) r2[t >> 5] = q;
    __syncthreads();
    float tv = 0.f;
    #pragma unroll
    for (int i = 0; i < 8; i++) tv += r2[i];
    float rstd = rsqrtf(tv * (1.f/512.f) + EPSF);
    float2 gg = *(const float2*)(g   + 2*t);
    float2 bb = *(const float2*)(bta + 2*t);
    float2 o;
    o.x = d0 * rstd * gg.x + bb.x;
    o.y = d1 * rstd * gg.y + bb.y;
    *(float2*)(y + (size_t)row * DN + 2*t) = o;
}

// ------------------------- K transpose: kT[b][j][m] = qkv[b,m,512+j] --------
__global__ __launch_bounds__(256) void kT_kernel(
    const float* __restrict__ qkv, float* __restrict__ kT)
{
    __shared__ float tile[32][33];
    int j0 = blockIdx.x * 32, m0 = blockIdx.y * 32, b = blockIdx.z;
    int tx = threadIdx.x & 31, ty = threadIdx.x >> 5;   // 32 x 8
    #pragma unroll
    for (int r = 0; r < 4; r++) {
        int m = m0 + ty + 8*r;
        tile[ty + 8*r][tx] = qkv[((size_t)b*Lz + m)*1536 + 512 + j0 + tx];
    }
    __syncthreads();
    #pragma unroll
    for (int r = 0; r < 4; r++) {
        int j = j0 + ty + 8*r;
        kT[((size_t)b*DN + j)*Lz + m0 + tx] = tile[tx][ty + 8*r];
    }
}

// ------------------------- tiled fp32 GEMM (128x128x16) ---------------------
__global__ __launch_bounds__(256) void gemm_kernel(
    const float* __restrict__ A, const float* __restrict__ W,
    const float* __restrict__ bias, const float* __restrict__ resid,
    float* __restrict__ C, int N, int K, int act)
{
    __shared__ __align__(16) float As[16*132];
    __shared__ __align__(16) float Bs[16*132];
    int bm = blockIdx.y, bn = blockIdx.x;
    int t = threadIdx.x;
    int tx = t & 15, ty = t >> 4;
    int row0 = ty * 8, col0 = tx * 8;
    const float* Ab = A + (size_t)bm * 128 * K;
    const float* Wb = W + (size_t)bn * 128;

    u64t acc[8][4];
    #pragma unroll
    for (int i = 0; i < 8; i++)
        #pragma unroll
        for (int j = 0; j < 4; j++) acc[i][j] = 0ull;

    for (int k0 = 0; k0 < K; k0 += 16) {
        #pragma unroll
        for (int r = 0; r < 2; r++) {
            int id = t + 256*r, arow = id >> 2, ac4 = id & 3;
            float4 v = *(const float4*)(Ab + (size_t)arow * K + k0 + ac4*4);
            As[(ac4*4+0)*132 + arow] = v.x;
            As[(ac4*4+1)*132 + arow] = v.y;
            As[(ac4*4+2)*132 + arow] = v.z;
            As[(ac4*4+3)*132 + arow] = v.w;
        }
        #pragma unroll
        for (int r = 0; r < 2; r++) {
            int id = t + 256*r, brow = id >> 5, bc4 = id & 31;
            float4 v = *(const float4*)(Wb + (size_t)(k0 + brow) * N + bc4*4);
            *(float4*)&Bs[brow*132 + bc4*4] = v;
        }
        __syncthreads();
        #pragma unroll
        for (int kk = 0; kk < 16; kk++) {
            float a[8];
            #pragma unroll
            for (int i = 0; i < 2; i++) {
                float4 v = *(const float4*)&As[kk*132 + row0 + 4*i];
                a[4*i] = v.x; a[4*i+1] = v.y; a[4*i+2] = v.z; a[4*i+3] = v.w;
            }
            u64t b2[4];
            {
                ulonglong2 q0 = *(const ulonglong2*)&Bs[kk*132 + col0];
                ulonglong2 q1 = *(const ulonglong2*)&Bs[kk*132 + col0 + 4];
                b2[0] = q0.x; b2[1] = q0.y; b2[2] = q1.x; b2[3] = q1.y;
            }
            #pragma unroll
            for (int i = 0; i < 8; i++) {
                u64t as = pk2(a[i], a[i]);
                #pragma unroll
                for (int j = 0; j < 4; j++) acc[i][j] = fma2(as, b2[j], acc[i][j]);
            }
        }
        __syncthreads();
    }

    float bcol[8];
    #pragma unroll
    for (int j = 0; j < 8; j++) bcol[j] = bias[bn*128 + col0 + j];

    #pragma unroll
    for (int i = 0; i < 8; i++) {
        size_t crow = (size_t)(bm*128 + row0 + i) * N + bn*128 + col0;
        #pragma unroll
        for (int j = 0; j < 4; j++) {
            float x0, x1; up2(acc[i][j], x0, x1);
            x0 += bcol[2*j]; x1 += bcol[2*j+1];
            if (act) { x0 = eluf(x0); x1 = eluf(x1); }
            if (resid) { x0 += resid[crow + 2*j]; x1 += resid[crow + 2*j + 1]; }
            float2 o; o.x = x0; o.y = x1;
            *(float2*)(C + crow + 2*j) = o;
        }
    }
}

// ------------------------- attention kernel: 2 tokens / block ----------------
#define ASMEM2 41856
__global__ __launch_bounds__(256) void egt_attn_kernel(
    const float* __restrict__ e, const float* __restrict__ maskp,
    const float* __restrict__ qkv, const float* __restrict__ kT,
    const float* __restrict__ lneg, const float* __restrict__ lneb,
    const float* __restrict__ WE,  const float* __restrict__ bE,
    const float* __restrict__ WG,  const float* __restrict__ bG,
    const float* __restrict__ WOe, const float* __restrict__ bOe,
    float* __restrict__ vatt, float* __restrict__ e2g)
{
    extern __shared__ __align__(16) float sm[];
    float* sq    = sm;             // 2*512
    float* sHs   = sq    + 1024;   // 2*8448
    float* sGs   = sHs   + 16896;  // 2*8448
    float* sMask = sGs   + 16896;  // 2*256
    float* sRmax = sMask + 512;    // 2*32
    float* sRinv = sRmax + 64;     // 2*32
    float* sWE   = sRinv + 64;     // 2048
    float* sWG   = sWE   + 2048;   // 2048
    float* sWOe  = sWG   + 2048;   // 2048
    float* sbE   = sWOe  + 2048;   // 32
    float* sbG   = sbE   + 32;     // 32
    float* sbOe  = sbG   + 32;     // 64
    float* sLg   = sbOe  + 64;     // 64
    float* sLb   = sLg   + 64;     // 64

    const int tid = threadIdx.x;
    const int b   = blockIdx.x >> 7;
    const int lp  = (blockIdx.x & 127) << 1;
    const size_t tok0 = (size_t)b * Lz + lp;
    const int m = tid;

    for (int i = tid; i < 1024; i += 256)
        sq[i] = qkv[(tok0 + (i >> 9))*1536 + (i & 511)];
    #pragma unroll
    for (int t = 0; t < 2; t++)
        sMask[t*256 + tid] = maskp[(tok0 + t)*Lz + tid];
    for (int i = tid; i < 2048; i += 256) { sWE[i] = WE[i]; sWG[i] = WG[i]; sWOe[i] = WOe[i]; }
    if (tid < 32)  { sbE[tid] = bE[tid]; sbG[tid] = bG[tid]; }
    if (tid < 64)  { sbOe[tid] = bOe[tid]; sLg[tid] = lneg[tid]; sLb[tid] = lneb[tid]; }
    __syncthreads();

    // ---- A_hat for both tokens (coalesced kT loads) ----
    {
        const float* kc = kT + (size_t)b*DN*Lz + m;
        const float* sq0 = sq, *sq1 = sq + 512;
        float a0[32], a1[32];
        #pragma unroll
        for (int h = 0; h < 32; h++) { a0[h] = 0.f; a1[h] = 0.f; }
        #pragma unroll 2
        for (int d = 0; d < 16; d++) {
            #pragma unroll
            for (int h = 0; h < 32; h++) {
                float kv = kc[(size_t)(d*32 + h) * Lz];
                a0[h] += sq0[d*32 + h] * kv;
                a1[h] += sq1[d*32 + h] * kv;
            }
        }
        #pragma unroll
        for (int h = 0; h < 32; h++) {
            sHs[m*33 + h]        = fminf(fmaxf(a0[h] * 0.25f, -5.f), 5.f);
            sHs[8448 + m*33 + h] = fminf(fmaxf(a1[h] * 0.25f, -5.f), 5.f);
        }
    }

    // ---- per token: e-LN + E/G; Hs += E, Gs = G ----
    for (int t = 0; t < 2; t++) {
        const float* erow = e + ((tok0 + t)*Lz + m) * DE;
        float ev[64]; float s0 = 0.f;
        #pragma unroll
        for (int i = 0; i < 16; i++) {
            float4 v = *(const float4*)(erow + 4*i);
            ev[4*i] = v.x; ev[4*i+1] = v.y; ev[4*i+2] = v.z; ev[4*i+3] = v.w;
            s0 += (v.x + v.y) + (v.z + v.w);
        }
        float mean = s0 * (1.f/64.f);
        float vs = 0.f;
        #pragma unroll
        for (int j = 0; j < 64; j++) { float d = ev[j] - mean; vs += d*d; }
        float rstd = rsqrtf(vs * (1.f/64.f) + EPSF);
        #pragma unroll
        for (int j = 0; j < 64; j++) ev[j] = (ev[j] - mean) * rstd * sLg[j] + sLb[j];

        u64t aE[16], aG[16];
        #pragma unroll
        for (int i = 0; i < 16; i++) {
            aE[i] = pk2(sbE[2*i], sbE[2*i+1]);
            aG[i] = pk2(sbG[2*i], sbG[2*i+1]);
        }
        #pragma unroll 8
        for (int j = 0; j < 64; j++) {
            u64t x = pk2(ev[j], ev[j]);
            const ulonglong2* we = (const ulonglong2*)(sWE + j*32);
            const ulonglong2* wg = (const ulonglong2*)(sWG + j*32);
            #pragma unroll
            for (int i4 = 0; i4 < 8; i4++) {
                ulonglong2 wa = we[i4];
                aE[2*i4]   = fma2(x, wa.x, aE[2*i4]);
                aE[2*i4+1] = fma2(x, wa.y, aE[2*i4+1]);
                ulonglong2 wb = wg[i4];
                aG[2*i4]   = fma2(x, wb.x, aG[2*i4]);
                aG[2*i4+1] = fma2(x, wb.y, aG[2*i4+1]);
            }
        }
        float* hs = sHs + t*8448 + m*33;
        float* gs = sGs + t*8448 + m*33;
        #pragma unroll
        for (int i = 0; i < 16; i++) {
            float E0, E1, g0, g1;
            up2(aE[i], E0, E1); up2(aG[i], g0, g1);
            hs[2*i] += E0; hs[2*i+1] += E1;
            gs[2*i]  = g0; gs[2*i+1]  = g1;
        }
    }
    __syncthreads();

    // ---- softmax stats ----
    {
        int warp = tid >> 5, lane = tid & 31;
        for (int t = 0; t < 2; t++) {
            const float* hs = sHs + t*8448;
            const float* mk = sMask + t*256;
            #pragma unroll
            for (int hh = 0; hh < 4; hh++) {
                int h = warp*4 + hh;
                float mx = -1e30f;
                for (int mm = lane; mm < 256; mm += 32)
                    mx = fmaxf(mx, hs[mm*33 + h] + mk[mm]);
                #pragma unroll
                for (int o = 16; o; o >>= 1) mx = fmaxf(mx, __shfl_xor_sync(0xffffffffu, mx, o));
                float ss = 0.f;
                for (int mm = lane; mm < 256; mm += 32)
                    ss += __expf(hs[mm*33 + h] + mk[mm] - mx);
                #pragma unroll
                for (int o = 16; o; o >>= 1) ss += __shfl_xor_sync(0xffffffffu, ss, o);
                if (lane == 0) { sRmax[t*32 + h] = mx; sRinv[t*32 + h] = 1.f / ss; }
            }
        }
    }
    __syncthreads();

    // ---- A_tild ----
    for (int t = 0; t < 2; t++) {
        float ms = sMask[t*256 + m];
        float* hs = sHs + t*8448 + m*33;
        float* gs = sGs + t*8448 + m*33;
        #pragma unroll 4
        for (int h = 0; h < 32; h++) {
            float p = __expf(hs[h] + ms - sRmax[t*32 + h]) * sRinv[t*32 + h];
            float gv = gs[h] + ms;
            gs[h] = p / (1.f + __expf(-gv));
        }
    }
    __syncthreads();

    // ---- V_att for both tokens ----
    {
        const int h = tid & 31;
        const int k0 = (tid >> 5) * 2;
        const float* vp = qkv + (size_t)b*Lz*1536 + 1024 + k0*32 + h;
        float a00 = 0.f, a01 = 0.f, a10 = 0.f, a11 = 0.f;
        #pragma unroll 4
        for (int mm = 0; mm < 256; mm++) {
            const float* p = vp + (size_t)mm * 1536;
            float p0 = p[0], p1 = p[32];
            float g0 = sGs[mm*33 + h];
            float g1 = sGs[8448 + mm*33 + h];
            a00 += g0 * p0; a01 += g0 * p1;
            a10 += g1 * p0; a11 += g1 * p1;
        }
        vatt[tok0*DN + k0*32 + h]            = a00;
        vatt[tok0*DN + (k0+1)*32 + h]        = a01;
        vatt[(tok0+1)*DN + k0*32 + h]        = a10;
        vatt[(tok0+1)*DN + (k0+1)*32 + h]    = a11;
    }

    // ---- e2 = Hs @ W_Oe + bOe + e ----
    for (int t = 0; t < 2; t++) {
        const float* hs = sHs + t*8448 + m*33;
        u64t e2p[32];
        #pragma unroll
        for (int i = 0; i < 32; i++) e2p[i] = pk2(sbOe[2*i], sbOe[2*i+1]);
        #pragma unroll 4
        for (int h = 0; h < 32; h++) {
            float hv = hs[h];
            u64t x = pk2(hv, hv);
            const ulonglong2* w = (const ulonglong2*)(sWOe + h*64);
            #pragma unroll
            for (int i4 = 0; i4 < 16; i4++) {
                ulonglong2 ww = w[i4];
                e2p[2*i4]   = fma2(x, ww.x, e2p[2*i4]);
                e2p[2*i4+1] = fma2(x, ww.y, e2p[2*i4+1]);
            }
        }
        const float* erow = e + ((tok0 + t)*Lz + m) * DE;
        float* dst = e2g + ((tok0 + t)*Lz + m) * DE;
        #pragma unroll
        for (int i = 0; i < 16; i++) {
            float a0, a1, c0, c1;
            up2(e2p[2*i],   a0, a1);
            up2(e2p[2*i+1], c0, c1);
            float4 ee = *(const float4*)(erow + 4*i);
            float4 v; v.x = a0 + ee.x; v.y = a1 + ee.y; v.z = c0 + ee.z; v.w = c1 + ee.w;
            *(float4*)(dst + 4*i) = v;
        }
    }
}

// ------------------------- e-FFN stage 1: LN + eff@W1 + b1, elu --------------
// tile 128 rows x 128 hidden, K=64.  LN fused into A staging.
#define F1SMEM 17152
__global__ __launch_bounds__(256) void ffn1_kernel(
    const float* __restrict__ e2g,
    const float* __restrict__ ffg, const float* __restrict__ ffb,
    const float* __restrict__ W1,  const float* __restrict__ b1,
    float* __restrict__ hid)
{
    extern __shared__ __align__(16) float smf[];
    float* As  = smf;           // 64*132  [k][row]
    float* Bs  = As + 8448;     // 64*132  [k][col]
    float* sb1 = Bs + 8448;     // 128
    float* sG  = sb1 + 128;     // 64
    float* sB  = sG + 64;       // 64

    const int t = threadIdx.x;
    const size_t row0g = (size_t)blockIdx.x * 128;

    // stage A (e2 tile) transposed
    #pragma unroll
    for (int r = 0; r < 8; r++) {
        int i = t + 256*r;                 // 2048 float4
        int row = i >> 4, c4 = i & 15;
        float4 v = *(const float4*)(e2g + (row0g + row)*DE + c4*4);
        As[(c4*4+0)*132 + row] = v.x;
        As[(c4*4+1)*132 + row] = v.y;
        As[(c4*4+2)*132 + row] = v.z;
        As[(c4*4+3)*132 + row] = v.w;
    }
    // stage W1 [64][128]
    #pragma unroll
    for (int r = 0; r < 8; r++) {
        int i = t + 256*r;                 // 2048 float4
        int row = i >> 5, c4 = i & 31;
        float4 v = *(const float4*)(W1 + row*128 + c4*4);
        *(float4*)&Bs[row*132 + c4*4] = v;
    }
    if (t < 128) sb1[t] = b1[t];
    if (t < 64)  { sG[t] = ffg[t]; sB[t] = ffb[t]; }
    __syncthreads();

    // fused LN of the 128 rows (threads 0..127)
    if (t < 128) {
        float s0 = 0.f;
        #pragma unroll
        for (int k = 0; k < 64; k++) s0 += As[k*132 + t];
        float mean = s0 * (1.f/64.f);
        float vs = 0.f;
        #pragma unroll
        for (int k = 0; k < 64; k++) { float d = As[k*132 + t] - mean; vs += d*d; }
        float rstd = rsqrtf(vs * (1.f/64.f) + EPSF);
        #pragma unroll
        for (int k = 0; k < 64; k++)
            As[k*132 + t] = (As[k*132 + t] - mean) * rstd * sG[k] + sB[k];
    }
    __syncthreads();

    const int tx = t & 15, ty = t >> 4;
    const int row0 = ty * 8, col0 = tx * 8;
    u64t acc[8][4];
    #pragma unroll
    for (int i = 0; i < 8; i++)
        #pragma unroll
        for (int j = 0; j < 4; j++) acc[i][j] = 0ull;

    #pragma unroll 8
    for (int kk = 0; kk < 64; kk++) {
        float a[8];
        #pragma unroll
        for (int i = 0; i < 2; i++) {
            float4 v = *(const float4*)&As[kk*132 + row0 + 4*i];
            a[4*i] = v.x; a[4*i+1] = v.y; a[4*i+2] = v.z; a[4*i+3] = v.w;
        }
        u64t b2[4];
        {
            ulonglong2 q0 = *(const ulonglong2*)&Bs[kk*132 + col0];
            ulonglong2 q1 = *(const ulonglong2*)&Bs[kk*132 + col0 + 4];
            b2[0] = q0.x; b2[1] = q0.y; b2[2] = q1.x; b2[3] = q1.y;
        }
        #pragma unroll
        for (int i = 0; i < 8; i++) {
            u64t as = pk2(a[i], a[i]);
            #pragma unroll
            for (int j = 0; j < 4; j++) acc[i][j] = fma2(as, b2[j], acc[i][j]);
        }
    }

    float bcol[8];
    #pragma unroll
    for (int j = 0; j < 8; j++) bcol[j] = sb1[col0 + j];
    #pragma unroll
    for (int i = 0; i < 8; i++) {
        float* dst = hid + (row0g + row0 + i)*128 + col0;
        #pragma unroll
        for (int j = 0; j < 4; j++) {
            float x0, x1; up2(acc[i][j], x0, x1);
            float2 o; o.x = eluf(x0 + bcol[2*j]); o.y = eluf(x1 + bcol[2*j+1]);
            *(float2*)(dst + 2*j) = o;
        }
    }
}

// ------------------------- e-FFN stage 2: hid@W2 + b2 + e2 -------------------
// tile 128 rows x 64 cols, K=128
#define F2SMEM 25664
__global__ __launch_bounds__(256) void ffn2_kernel(
    const float* __restrict__ hid, const float* __restrict__ e2g,
    const float* __restrict__ W2,  const float* __restrict__ b2v,
    float* __restrict__ e_out)
{
    extern __shared__ __align__(16) float smf[];
    float* As  = smf;           // 128*132 [k][row]
    float* Bs  = As + 16896;    // 128*68  [k][col]
    float* sb2 = Bs + 8704;     // 64

    const int t = threadIdx.x;
    const size_t row0g = (size_t)blockIdx.x * 128;

    #pragma unroll
    for (int r = 0; r < 16; r++) {
        int i = t + 256*r;                 // 4096 float4 = 128x128
        int row = i >> 5, c4 = i & 31;
        float4 v = *(const float4*)(hid + (row0g + row)*128 + c4*4);
        As[(c4*4+0)*132 + row] = v.x;
        As[(c4*4+1)*132 + row] = v.y;
        As[(c4*4+2)*132 + row] = v.z;
        As[(c4*4+3)*132 + row] = v.w;
    }
    #pragma unroll
    for (int r = 0; r < 8; r++) {
        int i = t + 256*r;                 // 2048 float4 = 128x64
        int row = i >> 4, c4 = i & 15;
        float4 v = *(const float4*)(W2 + row*64 + c4*4);
        *(float4*)&Bs[row*68 + c4*4] = v;
    }
    if (t < 64) sb2[t] = b2v[t];
    __syncthreads();

    const int tx = t & 7, ty = t >> 3;       // 8 col-groups, 32 row-groups
    const int row0 = ty * 4, col0 = tx * 8;
    u64t acc[4][4];
    #pragma unroll
    for (int i = 0; i < 4; i++)
        #pragma unroll
        for (int j = 0; j < 4; j++) acc[i][j] = 0ull;

    #pragma unroll 8
    for (int kk = 0; kk < 128; kk++) {
        float4 av = *(const float4*)&As[kk*132 + row0];
        float a[4] = {av.x, av.y, av.z, av.w};
        u64t b2[4];
        {
            ulonglong2 q0 = *(const ulonglong2*)&Bs[kk*68 + col0];
            ulonglong2 q1 = *(const ulonglong2*)&Bs[kk*68 + col0 + 4];
            b2[0] = q0.x; b2[1] = q0.y; b2[2] = q1.x; b2[3] = q1.y;
        }
        #pragma unroll
        for (int i = 0; i < 4; i++) {
            u64t as = pk2(a[i], a[i]);
            #pragma unroll
            for (int j = 0; j < 4; j++) acc[i][j] = fma2(as, b2[j], acc[i][j]);
        }
    }

    float bcol[8];
    #pragma unroll
    for (int j = 0; j < 8; j++) bcol[j] = sb2[col0 + j];
    #pragma unroll
    for (int i = 0; i < 4; i++) {
        size_t ro = (row0g + row0 + i)*DE + col0;
        #pragma unroll
        for (int j = 0; j < 4; j++) {
            float x0, x1; up2(acc[i][j], x0, x1);
            float2 rr = *(const float2*)(e2g + ro + 2*j);
            float2 o; o.x = x0 + bcol[2*j] + rr.x; o.y = x1 + bcol[2*j+1] + rr.y;
            *(float2*)(e_out + ro + 2*j) = o;
        }
    }
}

// ----------------------------- host launcher --------------------------------
extern "C" void kernel_launch(void* const* d_in, const int* in_sizes, int n_in,
                              void* d_out, int out_size)
{
    const float* h_in   = (const float*)d_in[0];
    const float* e_in   = (const float*)d_in[1];
    const float* mask   = (const float*)d_in[2];
    const float* ln_h_g = (const float*)d_in[3];
    const float* ln_h_b = (const float*)d_in[4];
    const float* ln_e_g = (const float*)d_in[5];
    const float* ln_e_b = (const float*)d_in[6];
    const float* ffn_ln_h_g = (const float*)d_in[7];
    const float* ffn_ln_h_b = (const float*)d_in[8];
    const float* ffn_ln_e_g = (const float*)d_in[9];
    const float* ffn_ln_e_b = (const float*)d_in[10];
    const float* W_qkv = (const float*)d_in[11];
    const float* b_qkv = (const float*)d_in[12];
    const float* W_E   = (const float*)d_in[13];
    const float* b_E   = (const float*)d_in[14];
    const float* W_G   = (const float*)d_in[15];
    const float* b_G   = (const float*)d_in[16];
    const float* W_Oh  = (const float*)d_in[17];
    const float* b_Oh  = (const float*)d_in[18];
    const float* W_h1  = (const float*)d_in[19];
    const float* b_h1  = (const float*)d_in[20];
    const float* W_h2  = (const float*)d_in[21];
    const float* b_h2  = (const float*)d_in[22];
    const float* W_Oe  = (const float*)d_in[23];
    const float* b_Oe  = (const float*)d_in[24];
    const float* W_e1  = (const float*)d_in[25];
    const float* b_e1  = (const float*)d_in[26];
    const float* W_e2  = (const float*)d_in[27];
    const float* b_e2  = (const float*)d_in[28];

    float* h_out = (float*)d_out;
    float* e_out = (float*)d_out + (size_t)NTOK * DN;

    float *hln, *qkv, *kT, *vatt, *h2b, *hff, *t1, *e2g, *hid;
    cudaGetSymbolAddress((void**)&hln,  g_hln);
    cudaGetSymbolAddress((void**)&qkv,  g_qkv);
    cudaGetSymbolAddress((void**)&kT,   g_kT);
    cudaGetSymbolAddress((void**)&vatt, g_vatt);
    cudaGetSymbolAddress((void**)&h2b,  g_h2);
    cudaGetSymbolAddress((void**)&hff,  g_hff);
    cudaGetSymbolAddress((void**)&t1,   g_t1);
    cudaGetSymbolAddress((void**)&e2g,  g_e2);
    cudaGetSymbolAddress((void**)&hid,  g_hid);

    cudaFuncSetAttribute(egt_attn_kernel, cudaFuncAttributeMaxDynamicSharedMemorySize, ASMEM2*4);
    cudaFuncSetAttribute(ffn1_kernel,     cudaFuncAttributeMaxDynamicSharedMemorySize, F1SMEM*4);
    cudaFuncSetAttribute(ffn2_kernel,     cudaFuncAttributeMaxDynamicSharedMemorySize, F2SMEM*4);

    // 1) h LayerNorm
    ln512_kernel<<<NTOK, 256>>>(h_in, ln_h_g, ln_h_b, hln);

    // 2) QKV
    {
        dim3 grid(1536/128, NTOK/128);
        gemm_kernel<<<grid, 256>>>(hln, W_qkv, b_qkv, nullptr, qkv, 1536, 512, 0);
    }

    // 3) K transpose
    {
        dim3 grid(DN/32, Lz/32, Bz);
        kT_kernel<<<grid, 256>>>(qkv, kT);
    }

    // 4) attention (2 tokens/block)
    egt_attn_kernel<<<NTOK/2, 256, ASMEM2*4>>>(
        e_in, mask, qkv, kT,
        ln_e_g, ln_e_b, W_E, b_E, W_G, b_G,
        W_Oe, b_Oe, vatt, e2g);

    // 5) e-FFN
    ffn1_kernel<<<(unsigned)(NROWS/128), 256, F1SMEM*4>>>(
        e2g, ffn_ln_e_g, ffn_ln_e_b, W_e1, b_e1, hid);
    ffn2_kernel<<<(unsigned)(NROWS/128), 256, F2SMEM*4>>>(
        hid, e2g, W_e2, b_e2, e_out);

    // 6) h2 = V_att @ W_Oh + b_Oh + h
    {
        dim3 grid(512/128, NTOK/128);
        gemm_kernel<<<grid, 256>>>(vatt, W_Oh, b_Oh, h_in, h2b, 512, 512, 0);
    }

    // 7) h FFN LN
    ln512_kernel<<<NTOK, 256>>>(h2b, ffn_ln_h_g, ffn_ln_h_b, hff);

    // 8) t1 = elu(h_ff @ W_h1 + b_h1)
    {
        dim3 grid(1024/128, NTOK/128);
        gemm_kernel<<<grid, 256>>>(hff, W_h1, b_h1, nullptr, t1, 1024, 512, 1);
    }

    // 9) h_out = t1 @ W_h2 + b_h2 + h2
    {
        dim3 grid(512/128, NTOK/128);
        gemm_kernel<<<grid, 256>>>(t1, W_h2, b_h2, h2b, h_out, 512, 1024, 0);
    }
}

// round 13
// speedup vs baseline: 1.2022x; 1.2022x over previous
#include <cuda_runtime.h>
#include <math.h>

#define Bz   32
#define Lz   256
#define DN   512
#define DE   64
#define FNh  1024
#define NTOK (Bz*Lz)
#define NROWS ((size_t)NTOK*Lz)
#define EPSF 1e-5f

typedef unsigned long long u64t;

__device__ __forceinline__ u64t pk2(float lo, float hi){
    u64t r; asm("mov.b64 %0,{%1,%2};" : "=l"(r) : "f"(lo), "f"(hi)); return r;
}
__device__ __forceinline__ void up2(u64t v, float& a, float& b){
    asm("mov.b64 {%0,%1},%2;" : "=f"(a), "=f"(b) : "l"(v));
}
__device__ __forceinline__ u64t fma2(u64t a, u64t b, u64t c){
    u64t d; asm("fma.rn.f32x2 %0,%1,%2,%3;" : "=l"(d) : "l"(a), "l"(b), "l"(c)); return d;
}
__device__ __forceinline__ float eluf(float x){
    return x > 0.f ? x : (__expf(x) - 1.f);
}

// ------------------------- scratch (device globals) -------------------------
__device__ __align__(16) float  g_hln [NTOK*DN];
__device__ __align__(16) float  g_qkv [(size_t)NTOK*3*DN];
__device__ __align__(16) float2 g_kT2 [(size_t)Bz*256*256];   // [b][j2][m] pairs of K
__device__ __align__(16) float  g_vatt[NTOK*DN];
__device__ __align__(16) float  g_h2  [NTOK*DN];
__device__ __align__(16) float  g_hff [NTOK*DN];
__device__ __align__(16) float  g_t1  [(size_t)NTOK*FNh];
__device__ __align__(16) float  g_e2  [NROWS*DE];

// ------------------------- LN over 512 ------------------
__global__ __launch_bounds__(256) void ln512_kernel(
    const float* __restrict__ x, const float* __restrict__ g,
    const float* __restrict__ bta, float* __restrict__ y)
{
    __shared__ float r1[8], r2[8];
    int row = blockIdx.x, t = threadIdx.x;
    const float* xr = x + (size_t)row * DN;
    float2 v = *(const float2*)(xr + 2*t);
    float s = v.x + v.y;
    #pragma unroll
    for (int o = 16; o; o >>= 1) s += __shfl_xor_sync(0xffffffffu, s, o);
    if ((t & 31) == 0) r1[t >> 5] = s;
    __syncthreads();
    float tot = 0.f;
    #pragma unroll
    for (int i = 0; i < 8; i++) tot += r1[i];
    float mean = tot * (1.f/512.f);
    float d0 = v.x - mean, d1 = v.y - mean;
    float q = d0*d0 + d1*d1;
    #pragma unroll
    for (int o = 16; o; o >>= 1) q += __shfl_xor_sync(0xffffffffu, q, o);
    if ((t & 31) == 0) r2[t >> 5] = q;
    __syncthreads();
    float tv = 0.f;
    #pragma unroll
    for (int i = 0; i < 8; i++) tv += r2[i];
    float rstd = rsqrtf(tv * (1.f/512.f) + EPSF);
    float2 gg = *(const float2*)(g   + 2*t);
    float2 bb = *(const float2*)(bta + 2*t);
    float2 o;
    o.x = d0 * rstd * gg.x + bb.x;
    o.y = d1 * rstd * gg.y + bb.y;
    *(float2*)(y + (size_t)row * DN + 2*t) = o;
}

// ------------------------- K transpose to pairs: kT2[b][j2][m] --------------
// tile[m_local][j_local]; pair j2 holds (K[2*j2], K[2*j2+1]) for token m.
__global__ __launch_bounds__(256) void kT_kernel(
    const float* __restrict__ qkv, float2* __restrict__ kT2)
{
    __shared__ float tile[32][33];
    int j0 = blockIdx.x * 32, m0 = blockIdx.y * 32, b = blockIdx.z;
    int tx = threadIdx.x & 31, ty = threadIdx.x >> 5;   // 32 x 8
    #pragma unroll
    for (int r = 0; r < 4; r++) {
        int m = m0 + ty + 8*r;
        tile[ty + 8*r][tx] = qkv[((size_t)b*Lz + m)*1536 + 512 + j0 + tx];
    }
    __syncthreads();
    #pragma unroll
    for (int r = 0; r < 2; r++) {
        int jl = ty + 8*r;                 // local pair index 0..15
        int j2 = (j0 >> 1) + jl;
        // tile is [m_local][j_local] — read m=tx, j=2*jl(+1)
        float2 v; v.x = tile[tx][2*jl]; v.y = tile[tx][2*jl + 1];
        kT2[((size_t)b*256 + j2)*256 + m0 + tx] = v;
    }
}

// ------------------------- tiled fp32 GEMM (128x128x16) ---------------------
__global__ __launch_bounds__(256) void gemm_kernel(
    const float* __restrict__ A, const float* __restrict__ W,
    const float* __restrict__ bias, const float* __restrict__ resid,
    float* __restrict__ C, int N, int K, int act)
{
    __shared__ __align__(16) float As[16*132];
    __shared__ __align__(16) float Bs[16*132];
    int bm = blockIdx.y, bn = blockIdx.x;
    int t = threadIdx.x;
    int tx = t & 15, ty = t >> 4;
    int row0 = ty * 8, col0 = tx * 8;
    const float* Ab = A + (size_t)bm * 128 * K;
    const float* Wb = W + (size_t)bn * 128;

    u64t acc[8][4];
    #pragma unroll
    for (int i = 0; i < 8; i++)
        #pragma unroll
        for (int j = 0; j < 4; j++) acc[i][j] = 0ull;

    for (int k0 = 0; k0 < K; k0 += 16) {
        #pragma unroll
        for (int r = 0; r < 2; r++) {
            int id = t + 256*r, arow = id >> 2, ac4 = id & 3;
            float4 v = *(const float4*)(Ab + (size_t)arow * K + k0 + ac4*4);
            As[(ac4*4+0)*132 + arow] = v.x;
            As[(ac4*4+1)*132 + arow] = v.y;
            As[(ac4*4+2)*132 + arow] = v.z;
            As[(ac4*4+3)*132 + arow] = v.w;
        }
        #pragma unroll
        for (int r = 0; r < 2; r++) {
            int id = t + 256*r, brow = id >> 5, bc4 = id & 31;
            float4 v = *(const float4*)(Wb + (size_t)(k0 + brow) * N + bc4*4);
            *(float4*)&Bs[brow*132 + bc4*4] = v;
        }
        __syncthreads();
        #pragma unroll
        for (int kk = 0; kk < 16; kk++) {
            float a[8];
            #pragma unroll
            for (int i = 0; i < 2; i++) {
                float4 v = *(const float4*)&As[kk*132 + row0 + 4*i];
                a[4*i] = v.x; a[4*i+1] = v.y; a[4*i+2] = v.z; a[4*i+3] = v.w;
            }
            u64t b2[4];
            {
                ulonglong2 q0 = *(const ulonglong2*)&Bs[kk*132 + col0];
                ulonglong2 q1 = *(const ulonglong2*)&Bs[kk*132 + col0 + 4];
                b2[0] = q0.x; b2[1] = q0.y; b2[2] = q1.x; b2[3] = q1.y;
            }
            #pragma unroll
            for (int i = 0; i < 8; i++) {
                u64t as = pk2(a[i], a[i]);
                #pragma unroll
                for (int j = 0; j < 4; j++) acc[i][j] = fma2(as, b2[j], acc[i][j]);
            }
        }
        __syncthreads();
    }

    float bcol[8];
    #pragma unroll
    for (int j = 0; j < 8; j++) bcol[j] = bias[bn*128 + col0 + j];

    #pragma unroll
    for (int i = 0; i < 8; i++) {
        size_t crow = (size_t)(bm*128 + row0 + i) * N + bn*128 + col0;
        #pragma unroll
        for (int j = 0; j < 4; j++) {
            float x0, x1; up2(acc[i][j], x0, x1);
            x0 += bcol[2*j]; x1 += bcol[2*j+1];
            if (act) { x0 = eluf(x0); x1 = eluf(x1); }
            if (resid) { x0 += resid[crow + 2*j]; x1 += resid[crow + 2*j + 1]; }
            float2 o; o.x = x0; o.y = x1;
            *(float2*)(C + crow + 2*j) = o;
        }
    }
}

// ------------------------- attention kernel: 512 thr, 2 tokens, fp32 ---------
#define ASMEM_FLOATS (8064 + 2*8448 + 2*8448)   // 41856 floats = 167,424 B
__global__ __launch_bounds__(512, 1) void egt_attn_kernel(
    const float* __restrict__ e, const float* __restrict__ maskp,
    const float* __restrict__ qkv, const float2* __restrict__ kT2,
    const float* __restrict__ lneg, const float* __restrict__ lneb,
    const float* __restrict__ WE,  const float* __restrict__ bE,
    const float* __restrict__ WG,  const float* __restrict__ bG,
    const float* __restrict__ WOe, const float* __restrict__ bOe,
    float* __restrict__ vatt, float* __restrict__ e2g)
{
    extern __shared__ __align__(16) float sm[];
    float* sq    = sm;             // 1024 (two Q rows)
    float* sMask = sq    + 1024;   // 512
    float* sRmax = sMask + 512;    // 64
    float* sRinv = sRmax + 64;     // 64
    float* sWE   = sRinv + 64;     // 2048
    float* sWG   = sWE   + 2048;   // 2048
    float* sWOe  = sWG   + 2048;   // 2048
    float* sbE   = sWOe  + 2048;   // 32
    float* sbG   = sbE   + 32;     // 32
    float* sbOe  = sbG   + 32;     // 64
    float* sLg   = sbOe  + 64;     // 64
    float* sLb   = sLg   + 64;     // 64  (8064 floats)
    float* sHs   = sm + 8064;      // [2][256*33]
    float* sGs   = sHs + 2*8448;   // [2][256*33]

    const int tid = threadIdx.x;
    const int tk  = tid >> 8;
    const int m   = tid & 255;
    const int b   = blockIdx.x >> 7;
    const int lp  = (blockIdx.x & 127) << 1;
    const size_t tok0 = (size_t)b * Lz + lp;
    const size_t tok  = tok0 + tk;

    for (int i = tid; i < 1024; i += 512)
        sq[i] = qkv[(tok0 + (i >> 9))*1536 + (i & 511)];
    sMask[tid] = maskp[tok*Lz + m];
    for (int i = tid; i < 2048; i += 512) { sWE[i] = WE[i]; sWG[i] = WG[i]; sWOe[i] = WOe[i]; }
    if (tid < 32)  { sbE[tid] = bE[tid]; sbG[tid] = bG[tid]; }
    else if (tid >= 64 && tid < 128) { int j = tid - 64; sbOe[j] = bOe[j]; }
    else if (tid >= 128 && tid < 192){ int j = tid - 128; sLg[j] = lneg[j]; sLb[j] = lneb[j]; }
    __syncthreads();

    // ---- A_hat: Q . K  (coalesced float2 kT2 loads) ----
    {
        const float2* kc = kT2 + (size_t)b*256*256 + m;
        const float* q0 = sq + tk*512;
        u64t a2[16];
        #pragma unroll
        for (int i = 0; i < 16; i++) a2[i] = 0ull;
        #pragma unroll 4
        for (int d = 0; d < 16; d++) {
            #pragma unroll
            for (int h2 = 0; h2 < 16; h2++) {
                float2 kv = kc[(size_t)(d*16 + h2)*256];
                u64t kk = pk2(kv.x, kv.y);
                u64t qq = *(const u64t*)(q0 + d*32 + 2*h2);
                a2[h2] = fma2(qq, kk, a2[h2]);
            }
        }
        float* hs = sHs + tk*8448 + m*33;
        #pragma unroll
        for (int i = 0; i < 16; i++) {
            float a0, a1; up2(a2[i], a0, a1);
            hs[2*i]   = fminf(fmaxf(a0 * 0.25f, -5.f), 5.f);
            hs[2*i+1] = fminf(fmaxf(a1 * 0.25f, -5.f), 5.f);
        }
    }

    // ---- e-LN, then E pass (Hs += E), then G pass (Gs = G) ----
    {
        const float* erow = e + (tok*Lz + m) * DE;
        float ev[64]; float s0 = 0.f;
        #pragma unroll
        for (int i = 0; i < 16; i++) {
            float4 v = *(const float4*)(erow + 4*i);
            ev[4*i] = v.x; ev[4*i+1] = v.y; ev[4*i+2] = v.z; ev[4*i+3] = v.w;
            s0 += (v.x + v.y) + (v.z + v.w);
        }
        float mean = s0 * (1.f/64.f);
        float vs = 0.f;
        #pragma unroll
        for (int j = 0; j < 64; j++) { float d = ev[j] - mean; vs += d*d; }
        float rstd = rsqrtf(vs * (1.f/64.f) + EPSF);
        #pragma unroll
        for (int j = 0; j < 64; j++) ev[j] = (ev[j] - mean) * rstd * sLg[j] + sLb[j];

        float* hs = sHs + tk*8448 + m*33;
        float* gs = sGs + tk*8448 + m*33;
        {
            u64t aE[16];
            #pragma unroll
            for (int i = 0; i < 16; i++) aE[i] = pk2(sbE[2*i], sbE[2*i+1]);
            #pragma unroll 8
            for (int j = 0; j < 64; j++) {
                u64t x = pk2(ev[j], ev[j]);
                const ulonglong2* we = (const ulonglong2*)(sWE + j*32);
                #pragma unroll
                for (int i4 = 0; i4 < 8; i4++) {
                    ulonglong2 wa = we[i4];
                    aE[2*i4]   = fma2(x, wa.x, aE[2*i4]);
                    aE[2*i4+1] = fma2(x, wa.y, aE[2*i4+1]);
                }
            }
            #pragma unroll
            for (int i = 0; i < 16; i++) {
                float E0, E1; up2(aE[i], E0, E1);
                hs[2*i] += E0; hs[2*i+1] += E1;
            }
        }
        {
            u64t aG[16];
            #pragma unroll
            for (int i = 0; i < 16; i++) aG[i] = pk2(sbG[2*i], sbG[2*i+1]);
            #pragma unroll 8
            for (int j = 0; j < 64; j++) {
                u64t x = pk2(ev[j], ev[j]);
                const ulonglong2* wg = (const ulonglong2*)(sWG + j*32);
                #pragma unroll
                for (int i4 = 0; i4 < 8; i4++) {
                    ulonglong2 wb = wg[i4];
                    aG[2*i4]   = fma2(x, wb.x, aG[2*i4]);
                    aG[2*i4+1] = fma2(x, wb.y, aG[2*i4+1]);
                }
            }
            #pragma unroll
            for (int i = 0; i < 16; i++) {
                float g0, g1; up2(aG[i], g0, g1);
                gs[2*i] = g0; gs[2*i+1] = g1;
            }
        }
    }
    __syncthreads();

    // ---- softmax stats: 16 warps, warp w -> token w>>3, heads (w&7)*4.. ----
    {
        int warp = tid >> 5, lane = tid & 31;
        int t_ = warp >> 3;
        const float* hs = sHs + t_*8448;
        const float* mk = sMask + t_*256;
        #pragma unroll
        for (int hh = 0; hh < 4; hh++) {
            int h = (warp & 7)*4 + hh;
            float mx = -1e30f;
            for (int mm = lane; mm < 256; mm += 32)
                mx = fmaxf(mx, hs[mm*33 + h] + mk[mm]);
            #pragma unroll
            for (int o = 16; o; o >>= 1) mx = fmaxf(mx, __shfl_xor_sync(0xffffffffu, mx, o));
            float ss = 0.f;
            for (int mm = lane; mm < 256; mm += 32)
                ss += __expf(hs[mm*33 + h] + mk[mm] - mx);
            #pragma unroll
            for (int o = 16; o; o >>= 1) ss += __shfl_xor_sync(0xffffffffu, ss, o);
            if (lane == 0) { sRmax[t_*32 + h] = mx; sRinv[t_*32 + h] = 1.f / ss; }
        }
    }
    __syncthreads();

    // ---- A_tild = softmax * sigmoid(G+mask) (into Gs) ----
    {
        float ms = sMask[tid];
        float* hs = sHs + tk*8448 + m*33;
        float* gs = sGs + tk*8448 + m*33;
        #pragma unroll 4
        for (int h = 0; h < 32; h++) {
            float p = __expf(hs[h] + ms - sRmax[tk*32 + h]) * sRinv[tk*32 + h];
            float gv = gs[h] + ms;
            gs[h] = p / (1.f + __expf(-gv));
        }
    }
    __syncthreads();

    // ---- V_att: per token, thread (h, k-pair) ----
    {
        const int h = m & 31;
        const int k0 = (m >> 5) * 2;
        const float* vp = qkv + (size_t)b*Lz*1536 + 1024 + k0*32 + h;
        const float* gs = sGs + tk*8448 + h;
        float a0 = 0.f, a1 = 0.f;
        #pragma unroll 4
        for (int mm = 0; mm < 256; mm++) {
            const float* p = vp + (size_t)mm * 1536;
            float g = gs[mm*33];
            a0 += g * p[0];
            a1 += g * p[32];
        }
        vatt[tok*DN + k0*32 + h]     = a0;
        vatt[tok*DN + (k0+1)*32 + h] = a1;
    }

    // ---- e2 = Hs @ W_Oe + bOe + e  -> scratch ----
    {
        const float* hs = sHs + tk*8448 + m*33;
        u64t e2p[32];
        #pragma unroll
        for (int i = 0; i < 32; i++) e2p[i] = pk2(sbOe[2*i], sbOe[2*i+1]);
        #pragma unroll 4
        for (int h = 0; h < 32; h++) {
            float hv = hs[h];
            u64t x = pk2(hv, hv);
            const ulonglong2* w = (const ulonglong2*)(sWOe + h*64);
            #pragma unroll
            for (int i4 = 0; i4 < 16; i4++) {
                ulonglong2 ww = w[i4];
                e2p[2*i4]   = fma2(x, ww.x, e2p[2*i4]);
                e2p[2*i4+1] = fma2(x, ww.y, e2p[2*i4+1]);
            }
        }
        const float* erow = e + (tok*Lz + m) * DE;
        float* dst = e2g + (tok*Lz + m) * DE;
        #pragma unroll
        for (int i = 0; i < 16; i++) {
            float a0, a1, c0, c1;
            up2(e2p[2*i],   a0, a1);
            up2(e2p[2*i+1], c0, c1);
            float4 ee = *(const float4*)(erow + 4*i);
            float4 v; v.x = a0 + ee.x; v.y = a1 + ee.y; v.z = c0 + ee.z; v.w = c1 + ee.w;
            *(float4*)(dst + 4*i) = v;
        }
    }
}

// ------------------------- fused e-FFN: 64-row tiles, hid stays in smem ------
#define FSMEM_FLOATS 26432
__global__ __launch_bounds__(256, 2) void effn_kernel(
    const float* __restrict__ e2g,
    const float* __restrict__ ffg, const float* __restrict__ ffb,
    const float* __restrict__ W1,  const float* __restrict__ b1,
    const float* __restrict__ W2,  const float* __restrict__ b2v,
    float* __restrict__ e_out)
{
    extern __shared__ __align__(16) float smf[];
    float* sE   = smf;            // [64 rows][68] raw e2
    float* sAln = sE   + 4352;    // [64 k][68]  LN'd transposed; later out staging
    float* sWb  = sAln + 4352;    // 8704: W1 [64][132], then W2 [128][68]
    float* sHid = sWb  + 8704;    // [128 hid][68 rows]
    float* sb1  = sHid + 8704;    // 128
    float* sb2  = sb1  + 128;     // 64
    float* sG   = sb2  + 64;      // 64
    float* sB   = sG   + 64;      // 64

    const int t = threadIdx.x;
    const size_t row0g = (size_t)blockIdx.x * 64;

    #pragma unroll
    for (int r = 0; r < 4; r++) {
        int i = t + 256*r;
        int row = i >> 4, c4 = i & 15;
        float4 v = *(const float4*)(e2g + (row0g + row)*DE + c4*4);
        *(float4*)&sE[row*68 + c4*4] = v;
    }
    #pragma unroll
    for (int r = 0; r < 8; r++) {
        int i = t + 256*r;
        int row = i >> 5, c4 = i & 31;
        float4 v = *(const float4*)(W1 + row*128 + c4*4);
        *(float4*)&sWb[row*132 + c4*4] = v;
    }
    if (t < 128) sb1[t] = b1[t];
    if (t < 64)  { sb2[t] = b2v[t]; sG[t] = ffg[t]; sB[t] = ffb[t]; }
    __syncthreads();

    if (t < 64) {
        const float* rowp = sE + t*68;
        float s0 = 0.f;
        #pragma unroll
        for (int k = 0; k < 64; k++) s0 += rowp[k];
        float mean = s0 * (1.f/64.f);
        float vs = 0.f;
        #pragma unroll
        for (int k = 0; k < 64; k++) { float d = rowp[k] - mean; vs += d*d; }
        float rstd = rsqrtf(vs * (1.f/64.f) + EPSF);
        #pragma unroll
        for (int k = 0; k < 64; k++)
            sAln[k*68 + t] = (rowp[k] - mean) * rstd * sG[k] + sB[k];
    }
    __syncthreads();

    const int rx = (t & 15) * 4;     // 4 rows
    const int cx = (t >> 4) * 8;     // 8 hidden cols
    {
        u64t acc[4][4];
        #pragma unroll
        for (int i = 0; i < 4; i++)
            #pragma unroll
            for (int j = 0; j < 4; j++) acc[i][j] = 0ull;
        #pragma unroll 8
        for (int k = 0; k < 64; k++) {
            float4 a4 = *(const float4*)&sAln[k*68 + rx];
            float a[4] = {a4.x, a4.y, a4.z, a4.w};
            ulonglong2 q0 = *(const ulonglong2*)&sWb[k*132 + cx];
            ulonglong2 q1 = *(const ulonglong2*)&sWb[k*132 + cx + 4];
            #pragma unroll
            for (int i = 0; i < 4; i++) {
                u64t as = pk2(a[i], a[i]);
                acc[i][0] = fma2(as, q0.x, acc[i][0]);
                acc[i][1] = fma2(as, q0.y, acc[i][1]);
                acc[i][2] = fma2(as, q1.x, acc[i][2]);
                acc[i][3] = fma2(as, q1.y, acc[i][3]);
            }
        }
        float c[4][8];
        #pragma unroll
        for (int i = 0; i < 4; i++)
            #pragma unroll
            for (int jp = 0; jp < 4; jp++) {
                float x0, x1; up2(acc[i][jp], x0, x1);
                c[i][2*jp]   = eluf(x0 + sb1[cx + 2*jp]);
                c[i][2*jp+1] = eluf(x1 + sb1[cx + 2*jp+1]);
            }
        #pragma unroll
        for (int j = 0; j < 8; j++) {
            float4 v; v.x = c[0][j]; v.y = c[1][j]; v.z = c[2][j]; v.w = c[3][j];
            *(float4*)&sHid[(cx + j)*68 + rx] = v;
        }
    }
    __syncthreads();

    #pragma unroll
    for (int r = 0; r < 8; r++) {
        int i = t + 256*r;
        int row = i >> 4, c4 = i & 15;
        float4 v = *(const float4*)(W2 + row*64 + c4*4);
        *(float4*)&sWb[row*68 + c4*4] = v;
    }
    __syncthreads();

    {
        const int cy = (t >> 4) * 4;  // 4 out cols
        u64t acc[4][2];
        #pragma unroll
        for (int i = 0; i < 4; i++) { acc[i][0] = 0ull; acc[i][1] = 0ull; }
        #pragma unroll 8
        for (int k = 0; k < 128; k++) {
            float4 a4 = *(const float4*)&sHid[k*68 + rx];
            float a[4] = {a4.x, a4.y, a4.z, a4.w};
            ulonglong2 q = *(const ulonglong2*)&sWb[k*68 + cy];
            #pragma unroll
            for (int i = 0; i < 4; i++) {
                u64t as = pk2(a[i], a[i]);
                acc[i][0] = fma2(as, q.x, acc[i][0]);
                acc[i][1] = fma2(as, q.y, acc[i][1]);
            }
        }
        __syncthreads();
        #pragma unroll
        for (int i = 0; i < 4; i++) {
            #pragma unroll
            for (int jp = 0; jp < 2; jp++) {
                float x0, x1; up2(acc[i][jp], x0, x1);
                x0 += sb2[cy + 2*jp]     + sE[(rx+i)*68 + cy + 2*jp];
                x1 += sb2[cy + 2*jp + 1] + sE[(rx+i)*68 + cy + 2*jp + 1];
                sAln[(rx+i)*68 + cy + 2*jp]     = x0;
                sAln[(rx+i)*68 + cy + 2*jp + 1] = x1;
            }
        }
    }
    __syncthreads();
    #pragma unroll
    for (int r = 0; r < 4; r++) {
        int i = t + 256*r;
        int row = i >> 4, c4 = i & 15;
        float4 v = *(const float4*)&sAln[row*68 + c4*4];
        *(float4*)(e_out + (row0g + row)*DE + c4*4) = v;
    }
}

// ----------------------------- host launcher --------------------------------
extern "C" void kernel_launch(void* const* d_in, const int* in_sizes, int n_in,
                              void* d_out, int out_size)
{
    const float* h_in   = (const float*)d_in[0];
    const float* e_in   = (const float*)d_in[1];
    const float* mask   = (const float*)d_in[2];
    const float* ln_h_g = (const float*)d_in[3];
    const float* ln_h_b = (const float*)d_in[4];
    const float* ln_e_g = (const float*)d_in[5];
    const float* ln_e_b = (const float*)d_in[6];
    const float* ffn_ln_h_g = (const float*)d_in[7];
    const float* ffn_ln_h_b = (const float*)d_in[8];
    const float* ffn_ln_e_g = (const float*)d_in[9];
    const float* ffn_ln_e_b = (const float*)d_in[10];
    const float* W_qkv = (const float*)d_in[11];
    const float* b_qkv = (const float*)d_in[12];
    const float* W_E   = (const float*)d_in[13];
    const float* b_E   = (const float*)d_in[14];
    const float* W_G   = (const float*)d_in[15];
    const float* b_G   = (const float*)d_in[16];
    const float* W_Oh  = (const float*)d_in[17];
    const float* b_Oh  = (const float*)d_in[18];
    const float* W_h1  = (const float*)d_in[19];
    const float* b_h1  = (const float*)d_in[20];
    const float* W_h2  = (const float*)d_in[21];
    const float* b_h2  = (const float*)d_in[22];
    const float* W_Oe  = (const float*)d_in[23];
    const float* b_Oe  = (const float*)d_in[24];
    const float* W_e1  = (const float*)d_in[25];
    const float* b_e1  = (const float*)d_in[26];
    const float* W_e2  = (const float*)d_in[27];
    const float* b_e2  = (const float*)d_in[28];

    float* h_out = (float*)d_out;
    float* e_out = (float*)d_out + (size_t)NTOK * DN;

    float *hln, *qkv, *vatt, *h2b, *hff, *t1, *e2g;
    float2 *kT2;
    cudaGetSymbolAddress((void**)&hln,  g_hln);
    cudaGetSymbolAddress((void**)&qkv,  g_qkv);
    cudaGetSymbolAddress((void**)&kT2,  g_kT2);
    cudaGetSymbolAddress((void**)&vatt, g_vatt);
    cudaGetSymbolAddress((void**)&h2b,  g_h2);
    cudaGetSymbolAddress((void**)&hff,  g_hff);
    cudaGetSymbolAddress((void**)&t1,   g_t1);
    cudaGetSymbolAddress((void**)&e2g,  g_e2);

    cudaFuncSetAttribute(egt_attn_kernel, cudaFuncAttributeMaxDynamicSharedMemorySize, ASMEM_FLOATS*4);
    cudaFuncSetAttribute(effn_kernel,     cudaFuncAttributeMaxDynamicSharedMemorySize, FSMEM_FLOATS*4);

    // 1) h LayerNorm
    ln512_kernel<<<NTOK, 256>>>(h_in, ln_h_g, ln_h_b, hln);

    // 2) QKV
    {
        dim3 grid(1536/128, NTOK/128);
        gemm_kernel<<<grid, 256>>>(hln, W_qkv, b_qkv, nullptr, qkv, 1536, 512, 0);
    }

    // 3) K transpose (pair-packed)
    {
        dim3 grid(DN/32, Lz/32, Bz);
        kT_kernel<<<grid, 256>>>(qkv, kT2);
    }

    // 4) attention (2 tokens, 512 threads, fp32)
    egt_attn_kernel<<<NTOK/2, 512, ASMEM_FLOATS*4>>>(
        e_in, mask, qkv, kT2,
        ln_e_g, ln_e_b, W_E, b_E, W_G, b_G,
        W_Oe, b_Oe, vatt, e2g);

    // 5) h2 = V_att @ W_Oh + b_Oh + h
    {
        dim3 grid(512/128, NTOK/128);
        gemm_kernel<<<grid, 256>>>(vatt, W_Oh, b_Oh, h_in, h2b, 512, 512, 0);
    }

    // 6) fused e-FFN  (launch #6 -> ncu -s 5 profiles this)
    effn_kernel<<<(unsigned)(NROWS/64), 256, FSMEM_FLOATS*4>>>(
        e2g, ffn_ln_e_g, ffn_ln_e_b, W_e1, b_e1, W_e2, b_e2, e_out);

    // 7) h FFN LN
    ln512_kernel<<<NTOK, 256>>>(h2b, ffn_ln_h_g, ffn_ln_h_b, hff);

    // 8) t1 = elu(h_ff @ W_h1 + b_h1)
    {
        dim3 grid(1024/128, NTOK/128);
        gemm_kernel<<<grid, 256>>>(hff, W_h1, b_h1, nullptr, t1, 1024, 512, 1);
    }

    // 9) h_out = t1 @ W_h2 + b_h2 + h2
    {
        dim3 grid(512/128, NTOK/128);
        gemm_kernel<<<grid, 256>>>(t1, W_h2, b_h2, h2b, h_out, 512, 1024, 0);
    }
}